// round 3
// baseline (speedup 1.0000x reference)
#include <cuda_runtime.h>

// Problem constants (fixed by the dataset)
#define NQ 65536          // number of query vectors (32*2048)
#define NE 1024           // codebook entries
#define D  64             // embedding dim
#define BM 128            // queries per block
#define BN 128            // codes per chunk
#define SST 132           // smem row stride (floats), pad vs 128 for store conflicts

// Output layout: tuple (loss, z_q_st, perplexity, idx) flattened to float32
#define O_LOSS 0
#define O_ZQ   1
#define O_PERP (1 + NQ * D)
#define O_IDX  (2 + NQ * D)

__device__ float        g_e2[NE];
__device__ unsigned int g_counts[NE];
__device__ double       g_loss;

// ---------------------------------------------------------------------------
// prep: per-code ||e||^2 with reference rounding (separate mul+add, ascending k),
// zero counts and loss accumulator. Runs every launch (graph-replayed).
// ---------------------------------------------------------------------------
__global__ void vq_prep(const float* __restrict__ cb) {
    int j = threadIdx.x;  // 1024 threads
    const float* r = cb + j * D;
    float s = 0.f;
#pragma unroll
    for (int k = 0; k < D; k++) {
        float v = __ldg(&r[k]);
        s = __fadd_rn(s, __fmul_rn(v, v));   // mimic jnp: square rounds, then add
    }
    g_e2[j] = s;
    g_counts[j] = 0u;
    if (j == 0) g_loss = 0.0;
}

// ---------------------------------------------------------------------------
// packed fp32x2 helpers (Blackwell FFMA2 — PTX-only path)
// ---------------------------------------------------------------------------
__device__ __forceinline__ unsigned long long pack2(float v) {
    unsigned long long r;
    asm("mov.b64 %0, {%1, %1};" : "=l"(r) : "f"(v));
    return r;
}
__device__ __forceinline__ unsigned long long fma2(unsigned long long a,
                                                   unsigned long long b,
                                                   unsigned long long c) {
    unsigned long long d;
    asm("fma.rn.f32x2 %0, %1, %2, %3;" : "=l"(d) : "l"(a), "l"(b), "l"(c));
    return d;
}

extern __shared__ float smem_dyn[];

// ---------------------------------------------------------------------------
// main: fused distance GEMM + argmin + gather + z_q_st store + loss partials
// grid = NQ/BM blocks of 256 threads. Dynamic smem: 2 * D * SST floats (66 KB).
// ---------------------------------------------------------------------------
__global__ void __launch_bounds__(256, 2)
vq_main(const float* __restrict__ z, const float* __restrict__ cb,
        float* __restrict__ out) {
    float* sz = smem_dyn;            // [D][SST]  z tile, transposed [k][q]
    float* se = smem_dyn + D * SST;  // [D][SST]  e chunk, transposed [k][j]
    __shared__ float szz[BM];        // per-query ||z||^2
    __shared__ int   sbest[BM];      // winning code per query
    __shared__ float swred[8];       // loss warp partials

    const int tid = threadIdx.x;
    const int tx  = tid & 15;        // 16 code-columns of threads
    const int ty  = tid >> 4;        // 16 query-rows of threads
    const int q0  = blockIdx.x * BM;

    // ---- load z tile, transposing [q][k] -> [k][q] (global loads coalesced) --
    {
        const float4* zg = (const float4*)(z + (size_t)q0 * D);
#pragma unroll
        for (int p = 0; p < 8; p++) {
            int q = p * 16 + ty;
            float4 v = zg[q * (D / 4) + tx];
            sz[(tx * 4 + 0) * SST + q] = v.x;
            sz[(tx * 4 + 1) * SST + q] = v.y;
            sz[(tx * 4 + 2) * SST + q] = v.z;
            sz[(tx * 4 + 3) * SST + q] = v.w;
        }
    }
    __syncthreads();

    // ---- per-query ||z||^2 with reference rounding (ascending k, mul then add)
    if (tid < BM) {
        float s = 0.f;
#pragma unroll
        for (int k = 0; k < D; k++) {
            float v = sz[k * SST + tid];
            s = __fadd_rn(s, __fmul_rn(v, v));
        }
        szz[tid] = s;
    }

    // running argmin per thread: 8 query rows (ty*4+.., 64+ty*4+..)
    float best[8];
    int   bidx[8];
#pragma unroll
    for (int i = 0; i < 8; i++) { best[i] = 3.4028235e38f; bidx[i] = 0; }

    const float* szp = sz + ty * 4;
    const float* sep = se + tx * 4;

    for (int ch = 0; ch < NE / BN; ch++) {
        __syncthreads();  // protects se overwrite; also publishes szz on iter 0
        {
            const float4* eg = (const float4*)(cb + (size_t)ch * BN * D);
#pragma unroll
            for (int p = 0; p < 8; p++) {
                int j = p * 16 + ty;
                float4 v = eg[j * (D / 4) + tx];
                se[(tx * 4 + 0) * SST + j] = v.x;
                se[(tx * 4 + 1) * SST + j] = v.y;
                se[(tx * 4 + 2) * SST + j] = v.z;
                se[(tx * 4 + 3) * SST + j] = v.w;
            }
        }
        __syncthreads();

        // 8x8 register tile via packed f32x2: acc pairs over adjacent codes.
        unsigned long long acc[8][4];
#pragma unroll
        for (int a = 0; a < 8; a++)
#pragma unroll
            for (int b = 0; b < 4; b++) acc[a][b] = 0ULL;

#pragma unroll 4
        for (int k = 0; k < D; k++) {
            float4 za = *(const float4*)(szp + k * SST);
            float4 zb = *(const float4*)(szp + k * SST + 64);
            ulonglong2 eA = *(const ulonglong2*)(sep + k * SST);
            ulonglong2 eB = *(const ulonglong2*)(sep + k * SST + 64);
            unsigned long long zp[8];
            zp[0] = pack2(za.x); zp[1] = pack2(za.y);
            zp[2] = pack2(za.z); zp[3] = pack2(za.w);
            zp[4] = pack2(zb.x); zp[5] = pack2(zb.y);
            zp[6] = pack2(zb.z); zp[7] = pack2(zb.w);
#pragma unroll
            for (int qi = 0; qi < 8; qi++) {
                acc[qi][0] = fma2(zp[qi], eA.x, acc[qi][0]);
                acc[qi][1] = fma2(zp[qi], eA.y, acc[qi][1]);
                acc[qi][2] = fma2(zp[qi], eB.x, acc[qi][2]);
                acc[qi][3] = fma2(zp[qi], eB.y, acc[qi][3]);
            }
        }

        // fold: s = fl(fl(zz+ee) - 2*dot), argmin with first-index semantics.
        // j visited in ascending order per (thread,query): strict < keeps first.
#pragma unroll
        for (int cp = 0; cp < 4; cp++) {
            int jb = ch * BN +
                     ((cp < 2) ? (tx * 4 + cp * 2) : (64 + tx * 4 + (cp - 2) * 2));
            float e2a = g_e2[jb];
            float e2b = g_e2[jb + 1];
#pragma unroll
            for (int qi = 0; qi < 8; qi++) {
                int qrow = (qi < 4) ? (ty * 4 + qi) : (64 + ty * 4 + (qi - 4));
                float zz = szz[qrow];
                float lo, hi;
                asm("mov.b64 {%0, %1}, %2;" : "=f"(lo), "=f"(hi) : "l"(acc[qi][cp]));
                float s0 = __fsub_rn(__fadd_rn(zz, e2a), 2.0f * lo);
                float s1 = __fsub_rn(__fadd_rn(zz, e2b), 2.0f * hi);
                if (s0 < best[qi]) { best[qi] = s0; bidx[qi] = jb; }
                if (s1 < best[qi]) { best[qi] = s1; bidx[qi] = jb + 1; }
            }
        }
    }

    // ---- cross-thread argmin reduction (16 thread-cols per query) -----------
    __syncthreads();
    float* rs = se;                       // overlay: [BM][16] scores
    int*   rj = (int*)(se + BM * 16);     //          [BM][16] indices
#pragma unroll
    for (int qi = 0; qi < 8; qi++) {
        int qrow = (qi < 4) ? (ty * 4 + qi) : (64 + ty * 4 + (qi - 4));
        rs[qrow * 16 + tx] = best[qi];
        rj[qrow * 16 + tx] = bidx[qi];
    }
    __syncthreads();
    if (tid < BM) {
        float bs = rs[tid * 16];
        int   bj = rj[tid * 16];
#pragma unroll
        for (int r = 1; r < 16; r++) {
            float s = rs[tid * 16 + r];
            int   j = rj[tid * 16 + r];
            if (s < bs || (s == bs && j < bj)) { bs = s; bj = j; }
        }
        sbest[tid] = bj;
        out[O_IDX + q0 + tid] = (float)bj;
        atomicAdd(&g_counts[bj], 1u);
    }
    __syncthreads();

    // ---- epilogue: gather codebook, write z_q_st, accumulate loss -----------
    // NOTE: out + O_ZQ is 4-byte-misaligned for float4 (O_ZQ == 1), so the
    // z_q_st stores must be scalar STG.32. Store volume is ~16 MB (~2 us);
    // the extra issue cost is noise vs the FMA-bound mainloop.
    float lsum = 0.f;
#pragma unroll
    for (int p = 0; p < 8; p++) {
        int ql = p * 16 + ty;
        int bj = sbest[ql];
        float4 cv = *(const float4*)(cb + (size_t)bj * D + tx * 4);
        float z0 = sz[(tx * 4 + 0) * SST + ql];
        float z1 = sz[(tx * 4 + 1) * SST + ql];
        float z2 = sz[(tx * 4 + 2) * SST + ql];
        float z3 = sz[(tx * 4 + 3) * SST + ql];
        float d0 = cv.x - z0, d1 = cv.y - z1, d2 = cv.z - z2, d3 = cv.w - z3;
        // z_q_st = z + (z_q - z), reference rounding order
        float* op = out + O_ZQ + (size_t)(q0 + ql) * D + tx * 4;
        op[0] = z0 + d0;
        op[1] = z1 + d1;
        op[2] = z2 + d2;
        op[3] = z3 + d3;
        lsum += d0 * d0 + d1 * d1 + d2 * d2 + d3 * d3;
    }
#pragma unroll
    for (int o = 16; o > 0; o >>= 1)
        lsum += __shfl_xor_sync(0xffffffffu, lsum, o);
    if ((tid & 31) == 0) swred[tid >> 5] = lsum;
    __syncthreads();
    if (tid == 0) {
        double t = 0.0;
#pragma unroll
        for (int w = 0; w < 8; w++) t += (double)swred[w];
        atomicAdd(&g_loss, t);
    }
}

// ---------------------------------------------------------------------------
// finish: perplexity from histogram + final loss scalar
// ---------------------------------------------------------------------------
__global__ void vq_finish(float* __restrict__ out) {
    __shared__ float wred[32];
    int t = threadIdx.x;  // 1024 threads
    float em = __fmul_rn((float)g_counts[t], 1.0f / (float)NQ);
    float s  = em * logf(__fadd_rn(em, 1e-10f));
#pragma unroll
    for (int o = 16; o > 0; o >>= 1)
        s += __shfl_xor_sync(0xffffffffu, s, o);
    if ((t & 31) == 0) wred[t >> 5] = s;
    __syncthreads();
    if (t < 32) {
        float v = wred[t];
#pragma unroll
        for (int o = 16; o > 0; o >>= 1)
            v += __shfl_xor_sync(0xffffffffu, v, o);
        if (t == 0) {
            out[O_PERP] = expf(-v);
            out[O_LOSS] = (float)(g_loss * (1.25 / (double)((size_t)NQ * D)));
        }
    }
}

// ---------------------------------------------------------------------------
extern "C" void kernel_launch(void* const* d_in, const int* in_sizes, int n_in,
                              void* d_out, int out_size) {
    (void)in_sizes; (void)n_in; (void)out_size;
    const float* z  = (const float*)d_in[0];
    const float* cb = (const float*)d_in[1];
    float* out = (float*)d_out;

    static bool attr_done = false;   // host-side, capture-safe, deterministic
    const int smem = 2 * D * SST * (int)sizeof(float);  // 67584 B
    if (!attr_done) {
        cudaFuncSetAttribute(vq_main, cudaFuncAttributeMaxDynamicSharedMemorySize, smem);
        attr_done = true;
    }

    vq_prep<<<1, NE>>>(cb);
    vq_main<<<NQ / BM, 256, smem>>>(z, cb, out);
    vq_finish<<<1, NE>>>(out);
}

// round 4
// speedup vs baseline: 1.0873x; 1.0873x over previous
#include <cuda_runtime.h>

// Problem constants (fixed by the dataset)
#define NQ 65536          // number of query vectors (32*2048)
#define NE 1024           // codebook entries
#define D  64             // embedding dim
#define BM 128            // queries per block
#define BN 128            // codes per chunk
#define SST 132           // smem row stride (floats), pad vs 128 for store conflicts

// Output layout: tuple (loss, z_q_st, perplexity, idx) flattened to float32
#define O_LOSS 0
#define O_ZQ   1
#define O_PERP (1 + NQ * D)
#define O_IDX  (2 + NQ * D)

__device__ float        g_e2[NE];
__device__ unsigned int g_counts[NE];
__device__ double       g_loss;

// ---------------------------------------------------------------------------
// prep: per-code ||e||^2 with reference rounding (separate mul+add, ascending
// k). Parallelized: 8 blocks x 128 threads (one thread per code), float4-
// batched loads for MLP, identical serial rounding chain.
// ---------------------------------------------------------------------------
__global__ void vq_prep(const float* __restrict__ cb) {
    int j = blockIdx.x * 128 + threadIdx.x;   // 0..1023
    const float4* r = (const float4*)(cb + (size_t)j * D);
    float4 v[16];
#pragma unroll
    for (int i = 0; i < 16; i++) v[i] = r[i];   // 16 independent LDG.128
    float s = 0.f;
#pragma unroll
    for (int i = 0; i < 16; i++) {
        s = __fadd_rn(s, __fmul_rn(v[i].x, v[i].x));
        s = __fadd_rn(s, __fmul_rn(v[i].y, v[i].y));
        s = __fadd_rn(s, __fmul_rn(v[i].z, v[i].z));
        s = __fadd_rn(s, __fmul_rn(v[i].w, v[i].w));
    }
    g_e2[j] = s;
    g_counts[j] = 0u;
    if (j == 0) g_loss = 0.0;
}

// ---------------------------------------------------------------------------
// packed fp32x2 helpers (Blackwell FFMA2 — PTX-only path)
// ---------------------------------------------------------------------------
__device__ __forceinline__ unsigned long long pack2(float v) {
    unsigned long long r;
    asm("mov.b64 %0, {%1, %1};" : "=l"(r) : "f"(v));
    return r;
}
__device__ __forceinline__ unsigned long long fma2(unsigned long long a,
                                                   unsigned long long b,
                                                   unsigned long long c) {
    unsigned long long d;
    asm("fma.rn.f32x2 %0, %1, %2, %3;" : "=l"(d) : "l"(a), "l"(b), "l"(c));
    return d;
}

extern __shared__ float smem_dyn[];

// ---------------------------------------------------------------------------
// main: fused distance GEMM + argmin + gather + z_q_st store + loss partials.
// grid = NQ/BM blocks of 256 threads.
// Dynamic smem: sz[D*SST] + se[2][D*SST] (double-buffered) + e2s[2][BN]
//             = 3*8448 + 256 floats = 102400 B. 2 CTAs/SM -> 200 KB < 228 KB.
// One __syncthreads per chunk: chunk ch+1 loads issue before chunk ch compute.
// ---------------------------------------------------------------------------
__global__ void __launch_bounds__(256, 2)
vq_main(const float* __restrict__ z, const float* __restrict__ cb,
        float* __restrict__ out) {
    float* sz  = smem_dyn;                  // [D][SST] z tile, [k][q]
    float* seb[2];
    seb[0] = smem_dyn + D * SST;            // [D][SST] e chunk buf 0
    seb[1] = smem_dyn + 2 * D * SST;        // [D][SST] e chunk buf 1
    float* e2s = smem_dyn + 3 * D * SST;    // [2][BN] staged ||e||^2
    __shared__ float szz[BM];
    __shared__ int   sbest[BM];
    __shared__ float swred[8];

    const int tid = threadIdx.x;
    const int tx  = tid & 15;        // 16 code-columns of threads
    const int ty  = tid >> 4;        // 16 query-rows of threads
    const int q0  = blockIdx.x * BM;

    // ---- prologue: z tile (transposed) + chunk 0 + e2 chunk 0 ---------------
    {
        const float4* zg = (const float4*)(z + (size_t)q0 * D);
#pragma unroll
        for (int p = 0; p < 8; p++) {
            int q = p * 16 + ty;
            float4 v = zg[q * (D / 4) + tx];
            sz[(tx * 4 + 0) * SST + q] = v.x;
            sz[(tx * 4 + 1) * SST + q] = v.y;
            sz[(tx * 4 + 2) * SST + q] = v.z;
            sz[(tx * 4 + 3) * SST + q] = v.w;
        }
        const float4* eg = (const float4*)(cb);
        float* se = seb[0];
#pragma unroll
        for (int p = 0; p < 8; p++) {
            int j = p * 16 + ty;
            float4 v = eg[j * (D / 4) + tx];
            se[(tx * 4 + 0) * SST + j] = v.x;
            se[(tx * 4 + 1) * SST + j] = v.y;
            se[(tx * 4 + 2) * SST + j] = v.z;
            se[(tx * 4 + 3) * SST + j] = v.w;
        }
        if (tid < BN) e2s[tid] = g_e2[tid];
    }
    __syncthreads();

    // ---- per-query ||z||^2, reference rounding (ascending k, mul then add) --
    if (tid < BM) {
        float s = 0.f;
#pragma unroll
        for (int k = 0; k < D; k++) {
            float v = sz[k * SST + tid];
            s = __fadd_rn(s, __fmul_rn(v, v));
        }
        szz[tid] = s;
    }
    // (szz published by the end-of-iteration sync of chunk 0? No — fold of
    //  chunk 0 needs szz. It is produced by threads tid<128 and consumed by
    //  all threads. Publish with a sync before the first fold: we fold after
    //  the compute loop of chunk 0; the barrier below covers it.)
    __syncthreads();

    float best[8];
    int   bidx[8];
#pragma unroll
    for (int i = 0; i < 8; i++) { best[i] = 3.4028235e38f; bidx[i] = 0; }

    const float* szp = sz + ty * 4;

    for (int ch = 0; ch < NE / BN; ch++) {
        const int buf = ch & 1;
        // ---- prefetch chunk ch+1 into the other buffer (LDG + STS) ----------
        if (ch < NE / BN - 1) {
            const float4* eg = (const float4*)(cb + (size_t)(ch + 1) * BN * D);
            float* sn = seb[buf ^ 1];
#pragma unroll
            for (int p = 0; p < 8; p++) {
                int j = p * 16 + ty;
                float4 v = eg[j * (D / 4) + tx];
                sn[(tx * 4 + 0) * SST + j] = v.x;
                sn[(tx * 4 + 1) * SST + j] = v.y;
                sn[(tx * 4 + 2) * SST + j] = v.z;
                sn[(tx * 4 + 3) * SST + j] = v.w;
            }
            if (tid < BN) e2s[(buf ^ 1) * BN + tid] = g_e2[(ch + 1) * BN + tid];
        }

        const float* sep = seb[buf] + tx * 4;

        // ---- 8x8 register tile via packed f32x2 (pairs over adjacent codes) -
        unsigned long long acc[8][4];
#pragma unroll
        for (int a = 0; a < 8; a++)
#pragma unroll
            for (int b = 0; b < 4; b++) acc[a][b] = 0ULL;

#pragma unroll 4
        for (int k = 0; k < D; k++) {
            float4 za = *(const float4*)(szp + k * SST);
            float4 zb = *(const float4*)(szp + k * SST + 64);
            ulonglong2 eA = *(const ulonglong2*)(sep + k * SST);
            ulonglong2 eB = *(const ulonglong2*)(sep + k * SST + 64);
            unsigned long long zp[8];
            zp[0] = pack2(za.x); zp[1] = pack2(za.y);
            zp[2] = pack2(za.z); zp[3] = pack2(za.w);
            zp[4] = pack2(zb.x); zp[5] = pack2(zb.y);
            zp[6] = pack2(zb.z); zp[7] = pack2(zb.w);
#pragma unroll
            for (int qi = 0; qi < 8; qi++) {
                acc[qi][0] = fma2(zp[qi], eA.x, acc[qi][0]);
                acc[qi][1] = fma2(zp[qi], eA.y, acc[qi][1]);
                acc[qi][2] = fma2(zp[qi], eB.x, acc[qi][2]);
                acc[qi][3] = fma2(zp[qi], eB.y, acc[qi][3]);
            }
        }

        // ---- fold: s = fl(fl(zz+ee) - 2*dot), first-index argmin ------------
        // j visited ascending per (thread,query): strict < keeps first index.
#pragma unroll
        for (int cp = 0; cp < 4; cp++) {
            int loc = (cp < 2) ? (tx * 4 + cp * 2) : (64 + tx * 4 + (cp - 2) * 2);
            int jb  = ch * BN + loc;
            float2 e2p = *(const float2*)(e2s + buf * BN + loc);
#pragma unroll
            for (int qi = 0; qi < 8; qi++) {
                int qrow = (qi < 4) ? (ty * 4 + qi) : (64 + ty * 4 + (qi - 4));
                float zz = szz[qrow];
                float lo, hi;
                asm("mov.b64 {%0, %1}, %2;" : "=f"(lo), "=f"(hi) : "l"(acc[qi][cp]));
                float s0 = __fsub_rn(__fadd_rn(zz, e2p.x), 2.0f * lo);
                float s1 = __fsub_rn(__fadd_rn(zz, e2p.y), 2.0f * hi);
                if (s0 < best[qi]) { best[qi] = s0; bidx[qi] = jb; }
                if (s1 < best[qi]) { best[qi] = s1; bidx[qi] = jb + 1; }
            }
        }
        __syncthreads();  // next-buffer stores visible; this buffer free to overwrite
    }

    // ---- cross-thread argmin reduction (16 thread-cols per query) -----------
    float* rs = seb[0];                       // overlay: [BM][16] scores
    int*   rj = (int*)(seb[0] + BM * 16);     //          [BM][16] indices
#pragma unroll
    for (int qi = 0; qi < 8; qi++) {
        int qrow = (qi < 4) ? (ty * 4 + qi) : (64 + ty * 4 + (qi - 4));
        rs[qrow * 16 + tx] = best[qi];
        rj[qrow * 16 + tx] = bidx[qi];
    }
    __syncthreads();
    if (tid < BM) {
        float bs = rs[tid * 16];
        int   bj = rj[tid * 16];
#pragma unroll
        for (int r = 1; r < 16; r++) {
            float s = rs[tid * 16 + r];
            int   j = rj[tid * 16 + r];
            if (s < bs || (s == bs && j < bj)) { bs = s; bj = j; }
        }
        sbest[tid] = bj;
        out[O_IDX + q0 + tid] = (float)bj;
        atomicAdd(&g_counts[bj], 1u);
    }
    __syncthreads();

    // ---- epilogue: gather codebook, write z_q_st, accumulate loss -----------
    // out + O_ZQ is 4-byte-misaligned for float4 (O_ZQ == 1): scalar STG.32.
    float lsum = 0.f;
#pragma unroll
    for (int p = 0; p < 8; p++) {
        int ql = p * 16 + ty;
        int bj = sbest[ql];
        float4 cv = *(const float4*)(cb + (size_t)bj * D + tx * 4);
        float z0 = sz[(tx * 4 + 0) * SST + ql];
        float z1 = sz[(tx * 4 + 1) * SST + ql];
        float z2 = sz[(tx * 4 + 2) * SST + ql];
        float z3 = sz[(tx * 4 + 3) * SST + ql];
        float d0 = cv.x - z0, d1 = cv.y - z1, d2 = cv.z - z2, d3 = cv.w - z3;
        float* op = out + O_ZQ + (size_t)(q0 + ql) * D + tx * 4;
        op[0] = z0 + d0;
        op[1] = z1 + d1;
        op[2] = z2 + d2;
        op[3] = z3 + d3;
        lsum += d0 * d0 + d1 * d1 + d2 * d2 + d3 * d3;
    }
#pragma unroll
    for (int o = 16; o > 0; o >>= 1)
        lsum += __shfl_xor_sync(0xffffffffu, lsum, o);
    if ((tid & 31) == 0) swred[tid >> 5] = lsum;
    __syncthreads();
    if (tid == 0) {
        double t = 0.0;
#pragma unroll
        for (int w = 0; w < 8; w++) t += (double)swred[w];
        atomicAdd(&g_loss, t);
    }
}

// ---------------------------------------------------------------------------
// finish: perplexity from histogram + final loss scalar
// ---------------------------------------------------------------------------
__global__ void vq_finish(float* __restrict__ out) {
    __shared__ float wred[32];
    int t = threadIdx.x;  // 1024 threads
    float em = __fmul_rn((float)g_counts[t], 1.0f / (float)NQ);
    float s  = em * logf(__fadd_rn(em, 1e-10f));
#pragma unroll
    for (int o = 16; o > 0; o >>= 1)
        s += __shfl_xor_sync(0xffffffffu, s, o);
    if ((t & 31) == 0) wred[t >> 5] = s;
    __syncthreads();
    if (t < 32) {
        float v = wred[t];
#pragma unroll
        for (int o = 16; o > 0; o >>= 1)
            v += __shfl_xor_sync(0xffffffffu, v, o);
        if (t == 0) {
            out[O_PERP] = expf(-v);
            out[O_LOSS] = (float)(g_loss * (1.25 / (double)((size_t)NQ * D)));
        }
    }
}

// ---------------------------------------------------------------------------
extern "C" void kernel_launch(void* const* d_in, const int* in_sizes, int n_in,
                              void* d_out, int out_size) {
    (void)in_sizes; (void)n_in; (void)out_size;
    const float* z  = (const float*)d_in[0];
    const float* cb = (const float*)d_in[1];
    float* out = (float*)d_out;

    static bool attr_done = false;   // host-side, capture-safe, deterministic
    const int smem = (3 * D * SST + 2 * BN) * (int)sizeof(float);  // 102400 B
    if (!attr_done) {
        cudaFuncSetAttribute(vq_main, cudaFuncAttributeMaxDynamicSharedMemorySize, smem);
        attr_done = true;
    }

    vq_prep<<<8, 128>>>(cb);
    vq_main<<<NQ / BM, 256, smem>>>(z, cb, out);
    vq_finish<<<1, NE>>>(out);
}